// round 17
// baseline (speedup 1.0000x reference)
#include <cuda_runtime.h>
#include <cuda_bf16.h>
#include <math.h>

#define N_NODES 1024
#define IN_F    256
#define OUT_F   128   // H*NH
#define TI      8     // target nodes per i-group
#define JHALF   512   // source nodes per block

// GL4[f][j] = float4 over heads (gl[j][hh*32+f], hh=0..3); row 32 = pad
__device__ float4 GL4[33 * N_NODES];
// GRD[opair][j] = (gr[2p][j], gr[2p+1][j])
__device__ float2 GRD[64 * N_NODES];
// gr natural layout [j][o]
__device__ float GRN[N_NODES * OUT_F];
// partial aggregation scratch
__device__ float PNUM[256][1024];
__device__ float PDEN[256][32];

// ---------------------------------------------------------------------------
// Packed fp32x2 helpers
// ---------------------------------------------------------------------------
__device__ __forceinline__ float2 fadd2(float2 a, float2 b) {
    float2 r;
    asm("add.rn.f32x2 %0, %1, %2;"
        : "=l"(*(unsigned long long*)&r)
        : "l"(*(const unsigned long long*)&a),
          "l"(*(const unsigned long long*)&b));
    return r;
}
__device__ __forceinline__ float2 ffma2(float2 a, float2 b, float2 c) {
    float2 r;
    asm("fma.rn.f32x2 %0, %1, %2, %3;"
        : "=l"(*(unsigned long long*)&r)
        : "l"(*(const unsigned long long*)&a),
          "l"(*(const unsigned long long*)&b),
          "l"(*(const unsigned long long*)&c));
    return r;
}
__device__ __forceinline__ float2 pack2(float x, float y) {
    float2 r;
    asm("mov.b64 %0, {%1, %2};"
        : "=l"(*(unsigned long long*)&r) : "f"(x), "f"(y));
    return r;
}
// |a| per packed half via 64-bit sign mask (2x LOP on the idle ALU pipe)
__device__ __forceinline__ float2 fabs2(float2 a) {
    float2 r;
    asm("and.b64 %0, %1, 0x7FFFFFFF7FFFFFFF;"
        : "=l"(*(unsigned long long*)&r)
        : "l"(*(const unsigned long long*)&a));
    return r;
}
__device__ __forceinline__ float2 lo4(float4 v) { return make_float2(v.x, v.y); }
__device__ __forceinline__ float2 hi4(float4 v) { return make_float2(v.z, v.w); }

// ---------------------------------------------------------------------------
// Kernel A v5 (unchanged): grid (16,8) = 128 blocks, 256 threads.
// ---------------------------------------------------------------------------
#define RS5 260
#define GEMM_SMEM_FLOATS ((32 + 64) * RS5)

__global__ void __launch_bounds__(256) gat_gemm(
    const float* __restrict__ h,
    const float* __restrict__ Wl,
    const float* __restrict__ Wr)
{
    extern __shared__ float smg[];
    float* ws = smg;              // [slot][k]
    float* hs = smg + 32 * RS5;   // [j_loc][k]

    const int t  = threadIdx.x;
    const int bx = blockIdx.x;
    const int by = blockIdx.y;
    const int j0 = bx * 64;
    const bool is_gl = (by < 4);

    const int oq = t & 7;
    const int jp = t >> 3;

    const float* __restrict__ Wsrc = is_gl ? Wl : Wr;
    const int og0 = is_gl ? 0 : ((by - 4) << 5);
#pragma unroll
    for (int it = 0; it < 8; it++) {
        int idx = t + it * 256;
        int row = idx >> 6, kq = idx & 63;
        int wrow = is_gl ? (((row >> 3) << 5) + (by << 3) + (row & 7))
                         : (og0 + row);
        *(float4*)&ws[row * RS5 + kq * 4] =
            *(const float4*)&Wsrc[wrow * IN_F + kq * 4];
    }
#pragma unroll
    for (int it = 0; it < 16; it++) {
        int idx = t + it * 256;
        int row = idx >> 6, kq = idx & 63;
        *(float4*)&hs[row * RS5 + kq * 4] =
            *(const float4*)&h[(j0 + row) * IN_F + kq * 4];
    }
    __syncthreads();

    const float* wp0 = ws + (oq     ) * RS5;
    const float* wp1 = ws + (oq +  8) * RS5;
    const float* wp2 = ws + (oq + 16) * RS5;
    const float* wp3 = ws + (oq + 24) * RS5;
    const float* hp0 = hs + (2 * jp    ) * RS5;
    const float* hp1 = hs + (2 * jp + 1) * RS5;

    float2 acc[8];
#pragma unroll
    for (int v = 0; v < 8; v++) acc[v] = make_float2(0.f, 0.f);

#pragma unroll 8
    for (int kg = 0; kg < 64; kg++) {
        float4 w0 = *(const float4*)&wp0[kg * 4];
        float4 w1 = *(const float4*)&wp1[kg * 4];
        float4 w2 = *(const float4*)&wp2[kg * 4];
        float4 w3 = *(const float4*)&wp3[kg * 4];
        float4 h0 = *(const float4*)&hp0[kg * 4];
        float4 h1 = *(const float4*)&hp1[kg * 4];
        float2 h0lo = lo4(h0), h0hi = hi4(h0);
        float2 h1lo = lo4(h1), h1hi = hi4(h1);
        acc[0] = ffma2(lo4(w0), h0lo, acc[0]);
        acc[1] = ffma2(lo4(w0), h1lo, acc[1]);
        acc[2] = ffma2(lo4(w1), h0lo, acc[2]);
        acc[3] = ffma2(lo4(w1), h1lo, acc[3]);
        acc[4] = ffma2(lo4(w2), h0lo, acc[4]);
        acc[5] = ffma2(lo4(w2), h1lo, acc[5]);
        acc[6] = ffma2(lo4(w3), h0lo, acc[6]);
        acc[7] = ffma2(lo4(w3), h1lo, acc[7]);
        acc[0] = ffma2(hi4(w0), h0hi, acc[0]);
        acc[1] = ffma2(hi4(w0), h1hi, acc[1]);
        acc[2] = ffma2(hi4(w1), h0hi, acc[2]);
        acc[3] = ffma2(hi4(w1), h1hi, acc[3]);
        acc[4] = ffma2(hi4(w2), h0hi, acc[4]);
        acc[5] = ffma2(hi4(w2), h1hi, acc[5]);
        acc[6] = ffma2(hi4(w3), h0hi, acc[6]);
        acc[7] = ffma2(hi4(w3), h1hi, acc[7]);
    }

    float sc[4][2];
#pragma unroll
    for (int v = 0; v < 4; v++)
#pragma unroll
        for (int jl = 0; jl < 2; jl++)
            sc[v][jl] = acc[v * 2 + jl].x + acc[v * 2 + jl].y;

    if (is_gl) {
        const int f = (by << 3) + oq;
#pragma unroll
        for (int jl = 0; jl < 2; jl++) {
            int j = j0 + 2 * jp + jl;
            GL4[(f << 10) + j] = make_float4(sc[0][jl], sc[1][jl], sc[2][jl], sc[3][jl]);
        }
    } else {
        float* grdf = (float*)GRD;
#pragma unroll
        for (int jl = 0; jl < 2; jl++) {
            int j = j0 + 2 * jp + jl;
#pragma unroll
            for (int v = 0; v < 4; v++) {
                int o = og0 + oq + 8 * v;
                GRN[(j << 7) + o] = sc[v][jl];
                grdf[((((o >> 1) << 10) + j) << 1) + (o & 1)] = sc[v][jl];
            }
        }
    }
}

// ---------------------------------------------------------------------------
// Kernel B: grid (2 j-halves, 128 i-groups), 1024 threads.
// Phase 1 v2: acc as float2 over ii-pairs; heads 0..2 use LOP-abs + FFMA2
// (alu+fma pipes), head 3 keeps scalar FFMA|abs| (fma only) -> pipes balanced.
// GL4 prefetched one f ahead (pad row makes f+1 always safe).
// ---------------------------------------------------------------------------
#define OFF_GRS  16384
#define OFF_RED  (OFF_GRS + 1024)
#define OFF_DOTR (OFF_RED + 1056)
#define OFF_CW   (OFF_DOTR + 32)
#define SMEM_FLOATS (OFF_CW + 64)

__global__ void __launch_bounds__(1024, 1) gat_main(
    const int*   __restrict__ adj,
    const float* __restrict__ attn_w,
    float*       __restrict__ out_unused)
{
    extern __shared__ float sm[];
    float4* a4     = (float4*)sm;            // 8 rows x 512 float4 (p values)
    float*  grs    = sm + OFF_GRS;           // [o][ii 0..7]
    float*  red    = sm + OFF_RED;           // 32 warps x 33
    float*  dotr_s = sm + OFF_DOTR;          // 32
    float2* cw     = (float2*)(sm + OFF_CW);

    const int t     = threadIdx.x;
    const int lane  = t & 31;
    const int warp  = t >> 5;
    const int jhb   = blockIdx.x;            // j-half
    const int ib    = blockIdx.y;            // i-group
    const int i0    = ib * TI;
    const int jbase = jhb * JHALF;
    const int jl    = lane & 15;
    const int fh    = lane >> 4;             // f-half AND ii-half role
    const int jloc  = (warp << 4) + jl;      // 0..511
    const int j     = jbase + jloc;          // global source node
    const int sidx  = ib * 2 + jhb;

    if (t < 32) { float w = attn_w[t]; cw[t] = make_float2(0.6f * w, 0.4f * w); }
    { int ii = t >> 7, oo = t & 127; grs[(oo << 3) + ii] = GRN[(i0 + ii) * OUT_F + oo]; }

    unsigned am = 0;   // 4 bits for ii in this thread's half
#pragma unroll
    for (int iil = 0; iil < 4; iil++)
        am |= (adj[(i0 + (fh << 2) + iil) * N_NODES + j] != 0) ? (1u << iil) : 0u;
    __syncthreads();

    // warp 0: dotr[ii][hh] = sum_f 0.6*w_f * gr[i0+ii][hh*32+f]
    if (t < 32) {
        int ii = t >> 2, hh = t & 3;
        float s = 0.f;
#pragma unroll 8
        for (int f = 0; f < 32; f++)
            s += cw[f].x * grs[(((hh << 5) + f) << 3) + ii];
        dotr_s[t] = s;   // index q = ii*4 + hh
    }

    // -------- Phase 1: accp[p*4+hh] packed over ii-pair p (ii 2p, 2p+1) -----
    float2 accp[16];
#pragma unroll
    for (int q = 0; q < 16; q++) accp[q] = make_float2(0.f, 0.f);
    float2 dlp[2];                 // (h0,h1), (h2,h3)
    dlp[0] = make_float2(0.f, 0.f);
    dlp[1] = make_float2(0.f, 0.f);

    const float4* grs4 = (const float4*)grs;
    const int fbase = fh << 4;
    float4 ga = GL4[(fbase << 10) + j];
#pragma unroll 2
    for (int fi = 0; fi < 16; fi++) {
        int f = fbase + fi;
        float4 gnext = GL4[((f + 1) << 10) + j];   // pad row at f=32
        float2 c = cw[f];
        float2 cx2 = pack2(c.x, c.x);
        float2 cy2 = pack2(c.y, c.y);
        dlp[0] = ffma2(cx2, lo4(ga), dlp[0]);
        dlp[1] = ffma2(cx2, hi4(ga), dlp[1]);
        float gaa[4] = {ga.x, ga.y, ga.z, ga.w};
#pragma unroll
        for (int hh = 0; hh < 4; hh++) {
            int o = (hh << 5) + f;
            float4 g0 = grs4[o * 2];         // ii 0..3
            float4 g1 = grs4[o * 2 + 1];     // ii 4..7
            float2 gl2 = pack2(gaa[hh], gaa[hh]);
            float2 x01 = fadd2(gl2, lo4(g0));
            float2 x23 = fadd2(gl2, hi4(g0));
            float2 x45 = fadd2(gl2, lo4(g1));
            float2 x67 = fadd2(gl2, hi4(g1));
            if (hh < 3) {
                // packed path: abs on alu pipe, fma2 on fma pipe
                accp[ 0 + hh] = ffma2(cy2, fabs2(x01), accp[ 0 + hh]);
                accp[ 4 + hh] = ffma2(cy2, fabs2(x23), accp[ 4 + hh]);
                accp[ 8 + hh] = ffma2(cy2, fabs2(x45), accp[ 8 + hh]);
                accp[12 + hh] = ffma2(cy2, fabs2(x67), accp[12 + hh]);
            } else {
                // scalar path: |x| is a free FFMA operand modifier
                accp[ 3].x = fmaf(c.y, fabsf(x01.x), accp[ 3].x);
                accp[ 3].y = fmaf(c.y, fabsf(x01.y), accp[ 3].y);
                accp[ 7].x = fmaf(c.y, fabsf(x23.x), accp[ 7].x);
                accp[ 7].y = fmaf(c.y, fabsf(x23.y), accp[ 7].y);
                accp[11].x = fmaf(c.y, fabsf(x45.x), accp[11].x);
                accp[11].y = fmaf(c.y, fabsf(x45.y), accp[11].y);
                accp[15].x = fmaf(c.y, fabsf(x67.x), accp[15].x);
                accp[15].y = fmaf(c.y, fabsf(x67.y), accp[15].y);
            }
        }
        ga = gnext;
    }
    // combine f-halves: lane l <-> l^16 hold the two partial sums for same j
    {
        float* af = (float*)accp;
#pragma unroll
        for (int q = 0; q < 32; q++) af[q] += __shfl_xor_sync(0xffffffffu, af[q], 16);
        float* dlf = (float*)dlp;
#pragma unroll
        for (int hh = 0; hh < 4; hh++) dlf[hh] += __shfl_xor_sync(0xffffffffu, dlf[hh], 16);
    }
    __syncthreads();   // dotr_s visible

    // -------- Phase 2: each lane-half finalizes its 4 ii --------
    const float* dlf = (const float*)dlp;
    float p[16];       // [iil*4 + hh], ii = fh*4 + iil
    {
        const float* af = (const float*)accp;
#pragma unroll
        for (int iil = 0; iil < 4; iil++) {
            int ii = (fh << 2) + iil;
            bool m = (am >> iil) & 1u;
#pragma unroll
            for (int hh = 0; hh < 4; hh++) {
                // accp[(ii>>1)*4+hh] component (ii&1)
                float av = af[((((ii >> 1) << 2) + hh) << 1) + (ii & 1)];
                float e = av + dlf[hh] + dotr_s[(ii << 2) + hh];
                p[iil * 4 + hh] = m ? __expf(e) : 0.f;
            }
        }
        // store p: row = hh*2 + fh, float4 over iil
#pragma unroll
        for (int hh = 0; hh < 4; hh++) {
            float4 v = make_float4(p[hh], p[4 + hh], p[8 + hh], p[12 + hh]);
            a4[(((hh << 1) + fh) << 9) + jloc] = v;
        }
    }
    // partial den: reduce over 16 j within each half-warp
#pragma unroll
    for (int qq = 0; qq < 16; qq++) {
        float v = p[qq];
#pragma unroll
        for (int d = 8; d; d >>= 1) v += __shfl_xor_sync(0xffffffffu, v, d);
        if (jl == 0) red[warp * 33 + (fh << 4) + qq] = v;
    }
    __syncthreads();   // p stores + red complete
    if (t < 32) {
        float s = 0.f;
#pragma unroll
        for (int w8 = 0; w8 < 32; w8++) s += red[w8 * 33 + t];
        PDEN[sidx][t] = s;     // q = ii*4 + hh
    }

    // -------- Phase 3: partial aggregation over this j-half --------
    const int opair = t >> 4;            // 0..63
    const int ihp   = (t >> 3) & 1;      // ii-half
    const int c     = t & 7;             // j-partition
    const int hh3   = opair >> 4;
    float2 accq[4];
#pragma unroll
    for (int v = 0; v < 4; v++) accq[v] = make_float2(0.f, 0.f);

    const float4* prow = a4 + (((hh3 << 1) + ihp) << 9);
    const float2* grp  = GRD + (opair << 10) + jbase;
#pragma unroll 4
    for (int g = 0; g < 64; g++) {
        int jl3 = (g << 3) + c;
        float4 pv = prow[jl3];           // 4 ii of this half
        float2 gr = grp[jl3];            // both o's of the pair
        float2 p01 = lo4(pv);
        float2 p23 = hi4(pv);
        float2 gx2 = pack2(gr.x, gr.x);
        float2 gy2 = pack2(gr.y, gr.y);
        accq[0] = ffma2(p01, gx2, accq[0]);
        accq[1] = ffma2(p23, gx2, accq[1]);
        accq[2] = ffma2(p01, gy2, accq[2]);
        accq[3] = ffma2(p23, gy2, accq[3]);
    }
    __syncthreads();                     // all a4 reads complete

    float a8[8] = {accq[0].x, accq[0].y, accq[1].x, accq[1].y,
                   accq[2].x, accq[2].y, accq[3].x, accq[3].y};
    float* part = sm;                    // [t][8] padded to 9
#pragma unroll
    for (int v = 0; v < 8; v++) part[t * 9 + v] = a8[v];
    __syncthreads();

    {
        int o2 = t & 127, ii2 = t >> 7;
        int op = o2 >> 1, oi = o2 & 1, ihq = ii2 >> 2, iil = ii2 & 3;
        float s = 0.f;
#pragma unroll
        for (int cc = 0; cc < 8; cc++)
            s += part[((op << 4) + (ihq << 3) + cc) * 9 + (oi << 2) + iil];
        PNUM[sidx][(ii2 << 7) + o2] = s;
    }
}

// ---------------------------------------------------------------------------
// Kernel C: combine the two j-half partials, normalize, ELU, write out.
// ---------------------------------------------------------------------------
__global__ void __launch_bounds__(1024) gat_combine(float* __restrict__ out)
{
    const int b = blockIdx.x;            // i-group
    const int t = threadIdx.x;
    const int ii2 = t >> 7, o2 = t & 127;
    float num = PNUM[b * 2][t] + PNUM[b * 2 + 1][t];
    int q = (ii2 << 2) + (o2 >> 5);
    float den = PDEN[b * 2][q] + PDEN[b * 2 + 1][q];
    float s = num / den;
    out[(b * TI + ii2) * OUT_F + o2] = (s > 0.f) ? s : expm1f(s);
}

// ---------------------------------------------------------------------------
extern "C" void kernel_launch(void* const* d_in, const int* in_sizes, int n_in,
                              void* d_out, int out_size)
{
    const float* h    = (const float*)d_in[0];
    const int*   adj  = (const int*)  d_in[1];
    const float* Wl   = (const float*)d_in[2];
    const float* Wr   = (const float*)d_in[3];
    const float* aw   = (const float*)d_in[4];
    float*       out  = (float*)d_out;

    size_t smg = GEMM_SMEM_FLOATS * sizeof(float);   // ~97.5 KB
    cudaFuncSetAttribute(gat_gemm, cudaFuncAttributeMaxDynamicSharedMemorySize, (int)smg);
    gat_gemm<<<dim3(16, 8), 256, smg>>>(h, Wl, Wr);

    size_t smem = SMEM_FLOATS * sizeof(float);       // ~74 KB
    cudaFuncSetAttribute(gat_main, cudaFuncAttributeMaxDynamicSharedMemorySize, (int)smem);
    gat_main<<<dim3(2, N_NODES / TI), 1024, smem>>>(adj, aw, out);

    gat_combine<<<N_NODES / TI, 1024>>>(out);
}